// round 15
// baseline (speedup 1.0000x reference)
#include <cuda_runtime.h>
#include <math.h>

// ---------------------------------------------------------------------------
// x: (128, 1, 512, 128) f32 ; patches 16x16 -> 256 patches/b, 32768 total.
// rfft2(16,16) -> 144 magnitudes; s = mean(log1p(mag)) = log(prod(1+mag))/144.
// out[b,p,e] = (s*u[e] + v[e]) * rsqrt(s^2*A + 2sB + C + eps) * gamma[e] + beta[e]
// Fused kernel: compute s for 16 patches, then stream the 16x768 out slice.
// Shared-memory aliasing (Z over staging tile) for high occupancy; epilogue
// mapping gives each thread a fixed column so constants load once.
// ---------------------------------------------------------------------------

#define NPATCH 32768
#define EMBED 768
#define WROWS 129
#define EPS 1e-5f

__device__ __align__(16) float g_g1[EMBED];   // u[e]*gamma[e]
__device__ __align__(16) float g_g2[EMBED];   // v[e]*gamma[e]
__device__ __align__(16) float g_bt[EMBED];   // beta[e]
__device__ float g_coef[4];                   // A, B, C

// ---------------------------------------------------------------------------
__device__ __forceinline__ float fsqrt_approx(float v) {
    float r;
    asm("sqrt.approx.f32 %0, %1;" : "=f"(r) : "f"(v));
    return r;
}

__device__ __forceinline__ float2 cmul(float2 a, float2 b) {
    return make_float2(fmaf(a.x, b.x, -a.y * b.y), fmaf(a.x, b.y, a.y * b.x));
}

// 16-point complex DIT FFT, fully unrolled, twiddles as immediates.
__device__ __forceinline__ void fft16(float2* a) {
    float2 t;
    t = a[1];  a[1]  = a[8];  a[8]  = t;
    t = a[2];  a[2]  = a[4];  a[4]  = t;
    t = a[3];  a[3]  = a[12]; a[12] = t;
    t = a[5];  a[5]  = a[10]; a[10] = t;
    t = a[7];  a[7]  = a[14]; a[14] = t;
    t = a[11]; a[11] = a[13]; a[13] = t;

    const float2 W16[8] = {
        { 1.0f,                  0.0f                 },
        { 0.92387953251128674f, -0.38268343236508978f },
        { 0.70710678118654757f, -0.70710678118654757f },
        { 0.38268343236508978f, -0.92387953251128674f },
        { 0.0f,                 -1.0f                 },
        {-0.38268343236508978f, -0.92387953251128674f },
        {-0.70710678118654757f, -0.70710678118654757f },
        {-0.92387953251128674f, -0.38268343236508978f },
    };

    #pragma unroll
    for (int s = 1; s <= 4; s++) {
        const int len  = 1 << s;
        const int half = len >> 1;
        const int step = 16 >> s;
        #pragma unroll
        for (int i = 0; i < 16; i += len) {
            #pragma unroll
            for (int j = 0; j < half; j++) {
                float2 w  = W16[j * step];
                float2 tt = cmul(w, a[i + j + half]);
                float2 u  = a[i + j];
                a[i + j]        = make_float2(u.x + tt.x, u.y + tt.y);
                a[i + j + half] = make_float2(u.x - tt.x, u.y - tt.y);
            }
        }
    }
}

// ---------------------------------------------------------------------------
__device__ __forceinline__ int sw_slot(int tr, int c) {
    // 3-bit XOR swizzle over float4 slots within a 32-slot row
    return tr * 32 + ((c & 24) | ((c ^ tr) & 7));
}

__global__ __launch_bounds__(256) void fused_kernel(const float* __restrict__ x,
                                                    float4* __restrict__ out) {
    // Aliased region: staging tile st (1024 float4 = 16384B) lives only until
    // phase-1 register loads; Z (16*9*17 float2 = 19584B) is born after a
    // __syncthreads. Overlap them to cut smem ~16KB -> higher occupancy.
    __shared__ __align__(16) float sbuf[4896];          // 19584 bytes
    float4* st = reinterpret_cast<float4*>(sbuf);
    float2 (*Z)[9][17] = reinterpret_cast<float2 (*)[9][17]>(sbuf);

    __shared__ float P[144];             // per-(patch,col) log partials
    __shared__ float SS[16], SI[16];     // per-patch s and rsqrt(var+eps)

    const int tid = threadIdx.x;

    // ---- stage: perfectly coalesced tile load ----
    const float4* gx = reinterpret_cast<const float4*>(x) + (size_t)blockIdx.x * 1024;
    #pragma unroll
    for (int k = 0; k < 4; k++) {
        int g  = k * 256 + tid;
        int tr = g >> 5, c = g & 31;
        st[sw_slot(tr, c)] = gx[g];
    }
    __syncthreads();

    // ---- phase 1a: pull patch rows from st into registers (threads 0..127) --
    float2 z[16];
    if (tid < 128) {
        const int lp  = tid >> 3;            // patch 0..15
        const int rr  = tid & 7;             // row pair 0..7
        const int tr0 = ((lp >> 3) << 4) + 2 * rr;
        const int w4  = (lp & 7) * 4;
        #pragma unroll
        for (int i = 0; i < 4; i++) {
            float4 re = st[sw_slot(tr0,     w4 + i)];
            float4 im = st[sw_slot(tr0 + 1, w4 + i)];
            z[i * 4 + 0] = make_float2(re.x, im.x);
            z[i * 4 + 1] = make_float2(re.y, im.y);
            z[i * 4 + 2] = make_float2(re.z, im.z);
            z[i * 4 + 3] = make_float2(re.w, im.w);
        }
    }
    __syncthreads();   // st fully consumed; safe to overwrite with Z

    // ---- phase 1b: FFT + Hermitian unpack, write Z (aliased over st) ----
    if (tid < 128) {
        const int lp = tid >> 3;
        const int rr = tid & 7;
        fft16(z);
        const float h = 0.03125f;            // 0.5 * ortho(1/16)
        #pragma unroll
        for (int k = 0; k < 9; k++) {
            const int m = (16 - k) & 15;
            float2 Zk = z[k], Zm = z[m];
            Z[lp][k][2 * rr]     = make_float2(h * (Zk.x + Zm.x),  h * (Zk.y - Zm.y));
            Z[lp][k][2 * rr + 1] = make_float2(h * (Zk.y + Zm.y), -h * (Zk.x - Zm.x));
        }
    }
    __syncthreads();

    // ---- phase 2: column FFTs + product of (1+mag), single log ----
    if (tid < 144) {
        const int p = tid / 9;
        const int k = tid - p * 9;
        float2 c[16];
        #pragma unroll
        for (int n = 0; n < 16; n++)
            c[n] = Z[p][k][n];
        fft16(c);

        float pr0 = 1.f, pr1 = 1.f;
        #pragma unroll
        for (int n = 0; n < 16; n += 2) {
            float m0 = fmaf(c[n].x,   c[n].x,   c[n].y   * c[n].y);
            float m1 = fmaf(c[n+1].x, c[n+1].x, c[n+1].y * c[n+1].y);
            pr0 *= (1.0f + fsqrt_approx(m0));
            pr1 *= (1.0f + fsqrt_approx(m1));
        }
        P[tid] = __logf(pr0 * pr1);
    }
    __syncthreads();

    // ---- per-patch reduce + layernorm scalar ----
    if (tid < 16) {
        float s = 0.f;
        #pragma unroll
        for (int k = 0; k < 9; k++)
            s += P[tid * 9 + k];
        s *= (1.0f / 144.0f);
        const float A = g_coef[0], B = g_coef[1], C = g_coef[2];
        SS[tid] = s;
        SI[tid] = rsqrtf(fmaf(fmaf(A, s, 2.0f * B), s, C) + EPS);
    }
    __syncthreads();

    // ---- epilogue: fixed column per thread, constants loaded ONCE ----
    if (tid < 192) {
        const float4 G1 = reinterpret_cast<const float4*>(g_g1)[tid];
        const float4 G2 = reinterpret_cast<const float4*>(g_g2)[tid];
        const float4 BE = reinterpret_cast<const float4*>(g_bt)[tid];
        float4* orow = out + (size_t)blockIdx.x * 16 * 192 + tid;

        #pragma unroll
        for (int r = 0; r < 16; r++) {
            const float s   = SS[r];
            const float inv = SI[r];
            float4 o;
            o.x = fmaf(fmaf(s, G1.x, G2.x), inv, BE.x);
            o.y = fmaf(fmaf(s, G1.y, G2.y), inv, BE.y);
            o.z = fmaf(fmaf(s, G1.z, G2.z), inv, BE.z);
            o.w = fmaf(fmaf(s, G1.w, G2.w), inv, BE.w);
            __stcs(orow + r * 192, o);
        }
    }
}

// ---------------------------------------------------------------------------
// prep: constants for the collapsed matmul+layernorm (single block)
// ---------------------------------------------------------------------------
__device__ __forceinline__ float block_sum768(float v, float* sh) {
    const int lane = threadIdx.x & 31;
    const int wid  = threadIdx.x >> 5;
    #pragma unroll
    for (int o = 16; o; o >>= 1)
        v += __shfl_xor_sync(0xffffffffu, v, o);
    __syncthreads();
    if (lane == 0) sh[wid] = v;
    __syncthreads();
    if (threadIdx.x == 0) {
        float tt = 0.f;
        #pragma unroll
        for (int i = 0; i < 24; i++) tt += sh[i];
        sh[24] = tt;
    }
    __syncthreads();
    return sh[24];
}

__global__ __launch_bounds__(768) void prep_kernel(const float* __restrict__ W,
                                                   const float* __restrict__ b,
                                                   const float* __restrict__ gamma,
                                                   const float* __restrict__ beta) {
    __shared__ float sh[32];
    const int e = threadIdx.x;

    float wsum = 0.f;
    #pragma unroll 4
    for (int k = 0; k < WROWS; k++)
        wsum += W[k * EMBED + e];
    const float be = b[e];

    const float meanW = block_sum768(wsum, sh) * (1.0f / EMBED);
    const float meanb = block_sum768(be,   sh) * (1.0f / EMBED);

    const float u = wsum - meanW;
    const float v = be   - meanb;

    const float A = block_sum768(u * u, sh) * (1.0f / EMBED);
    const float B = block_sum768(u * v, sh) * (1.0f / EMBED);
    const float C = block_sum768(v * v, sh) * (1.0f / EMBED);

    g_g1[e] = u * gamma[e];
    g_g2[e] = v * gamma[e];
    g_bt[e] = beta[e];
    if (e == 0) {
        g_coef[0] = A; g_coef[1] = B; g_coef[2] = C;
    }
}

// ---------------------------------------------------------------------------
extern "C" void kernel_launch(void* const* d_in, const int* in_sizes, int n_in,
                              void* d_out, int out_size) {
    const float* x     = (const float*)d_in[0];
    const float* W     = (const float*)d_in[1];
    const float* b     = (const float*)d_in[2];
    const float* gamma = (const float*)d_in[3];
    const float* beta  = (const float*)d_in[4];

    prep_kernel<<<1, EMBED>>>(W, b, gamma, beta);
    fused_kernel<<<NPATCH / 16, 256>>>(x, (float4*)d_out);
}

// round 16
// speedup vs baseline: 1.0266x; 1.0266x over previous
#include <cuda_runtime.h>
#include <math.h>

// ---------------------------------------------------------------------------
// x: (128, 1, 512, 128) f32 ; patches 16x16 -> 256 patches/b, 32768 total.
// rfft2(16,16) -> 144 magnitudes; s = mean(log1p(mag)) = log(prod(1+mag))/144.
// out[b,p,e] = (s*u[e] + v[e]) * rsqrt(s^2*A + 2sB + C + eps) * gamma[e] + beta[e]
// Fused kernel: compute s for 16 patches, then stream the 16x768 out slice.
// Shared-memory aliasing (Z over staging tile) for high occupancy; epilogue
// mapping gives each thread a fixed column so constants load once.
// ---------------------------------------------------------------------------

#define NPATCH 32768
#define EMBED 768
#define WROWS 129
#define EPS 1e-5f

__device__ __align__(16) float g_g1[EMBED];   // u[e]*gamma[e]
__device__ __align__(16) float g_g2[EMBED];   // v[e]*gamma[e]
__device__ __align__(16) float g_bt[EMBED];   // beta[e]
__device__ float g_coef[4];                   // A, B, C

// ---------------------------------------------------------------------------
__device__ __forceinline__ float fsqrt_approx(float v) {
    float r;
    asm("sqrt.approx.f32 %0, %1;" : "=f"(r) : "f"(v));
    return r;
}

__device__ __forceinline__ float2 cmul(float2 a, float2 b) {
    return make_float2(fmaf(a.x, b.x, -a.y * b.y), fmaf(a.x, b.y, a.y * b.x));
}

// 16-point complex DIT FFT, fully unrolled, twiddles as immediates.
__device__ __forceinline__ void fft16(float2* a) {
    float2 t;
    t = a[1];  a[1]  = a[8];  a[8]  = t;
    t = a[2];  a[2]  = a[4];  a[4]  = t;
    t = a[3];  a[3]  = a[12]; a[12] = t;
    t = a[5];  a[5]  = a[10]; a[10] = t;
    t = a[7];  a[7]  = a[14]; a[14] = t;
    t = a[11]; a[11] = a[13]; a[13] = t;

    const float2 W16[8] = {
        { 1.0f,                  0.0f                 },
        { 0.92387953251128674f, -0.38268343236508978f },
        { 0.70710678118654757f, -0.70710678118654757f },
        { 0.38268343236508978f, -0.92387953251128674f },
        { 0.0f,                 -1.0f                 },
        {-0.38268343236508978f, -0.92387953251128674f },
        {-0.70710678118654757f, -0.70710678118654757f },
        {-0.92387953251128674f, -0.38268343236508978f },
    };

    #pragma unroll
    for (int s = 1; s <= 4; s++) {
        const int len  = 1 << s;
        const int half = len >> 1;
        const int step = 16 >> s;
        #pragma unroll
        for (int i = 0; i < 16; i += len) {
            #pragma unroll
            for (int j = 0; j < half; j++) {
                float2 w  = W16[j * step];
                float2 tt = cmul(w, a[i + j + half]);
                float2 u  = a[i + j];
                a[i + j]        = make_float2(u.x + tt.x, u.y + tt.y);
                a[i + j + half] = make_float2(u.x - tt.x, u.y - tt.y);
            }
        }
    }
}

// ---------------------------------------------------------------------------
__device__ __forceinline__ int sw_slot(int tr, int c) {
    // 3-bit XOR swizzle over float4 slots within a 32-slot row
    return tr * 32 + ((c & 24) | ((c ^ tr) & 7));
}

__global__ __launch_bounds__(256) void fused_kernel(const float* __restrict__ x,
                                                    float4* __restrict__ out) {
    // Aliased region: staging tile st (1024 float4 = 16384B) lives only until
    // phase-1 register loads; Z (16*9*17 float2 = 19584B) is born after a
    // __syncthreads. Overlap them to cut smem ~16KB -> higher occupancy.
    __shared__ __align__(16) float sbuf[4896];          // 19584 bytes
    float4* st = reinterpret_cast<float4*>(sbuf);
    float2 (*Z)[9][17] = reinterpret_cast<float2 (*)[9][17]>(sbuf);

    __shared__ float P[144];             // per-(patch,col) log partials
    __shared__ float SS[16], SI[16];     // per-patch s and rsqrt(var+eps)

    const int tid = threadIdx.x;

    // ---- stage: perfectly coalesced tile load ----
    const float4* gx = reinterpret_cast<const float4*>(x) + (size_t)blockIdx.x * 1024;
    #pragma unroll
    for (int k = 0; k < 4; k++) {
        int g  = k * 256 + tid;
        int tr = g >> 5, c = g & 31;
        st[sw_slot(tr, c)] = gx[g];
    }
    __syncthreads();

    // ---- phase 1a: pull patch rows from st into registers (threads 0..127) --
    float2 z[16];
    if (tid < 128) {
        const int lp  = tid >> 3;            // patch 0..15
        const int rr  = tid & 7;             // row pair 0..7
        const int tr0 = ((lp >> 3) << 4) + 2 * rr;
        const int w4  = (lp & 7) * 4;
        #pragma unroll
        for (int i = 0; i < 4; i++) {
            float4 re = st[sw_slot(tr0,     w4 + i)];
            float4 im = st[sw_slot(tr0 + 1, w4 + i)];
            z[i * 4 + 0] = make_float2(re.x, im.x);
            z[i * 4 + 1] = make_float2(re.y, im.y);
            z[i * 4 + 2] = make_float2(re.z, im.z);
            z[i * 4 + 3] = make_float2(re.w, im.w);
        }
    }
    __syncthreads();   // st fully consumed; safe to overwrite with Z

    // ---- phase 1b: FFT + Hermitian unpack, write Z (aliased over st) ----
    if (tid < 128) {
        const int lp = tid >> 3;
        const int rr = tid & 7;
        fft16(z);
        const float h = 0.03125f;            // 0.5 * ortho(1/16)
        #pragma unroll
        for (int k = 0; k < 9; k++) {
            const int m = (16 - k) & 15;
            float2 Zk = z[k], Zm = z[m];
            Z[lp][k][2 * rr]     = make_float2(h * (Zk.x + Zm.x),  h * (Zk.y - Zm.y));
            Z[lp][k][2 * rr + 1] = make_float2(h * (Zk.y + Zm.y), -h * (Zk.x - Zm.x));
        }
    }
    __syncthreads();

    // ---- phase 2: column FFTs + product of (1+mag), single log ----
    if (tid < 144) {
        const int p = tid / 9;
        const int k = tid - p * 9;
        float2 c[16];
        #pragma unroll
        for (int n = 0; n < 16; n++)
            c[n] = Z[p][k][n];
        fft16(c);

        float pr0 = 1.f, pr1 = 1.f;
        #pragma unroll
        for (int n = 0; n < 16; n += 2) {
            float m0 = fmaf(c[n].x,   c[n].x,   c[n].y   * c[n].y);
            float m1 = fmaf(c[n+1].x, c[n+1].x, c[n+1].y * c[n+1].y);
            pr0 *= (1.0f + fsqrt_approx(m0));
            pr1 *= (1.0f + fsqrt_approx(m1));
        }
        P[tid] = __logf(pr0 * pr1);
    }
    __syncthreads();

    // ---- per-patch reduce + layernorm scalar ----
    if (tid < 16) {
        float s = 0.f;
        #pragma unroll
        for (int k = 0; k < 9; k++)
            s += P[tid * 9 + k];
        s *= (1.0f / 144.0f);
        const float A = g_coef[0], B = g_coef[1], C = g_coef[2];
        SS[tid] = s;
        SI[tid] = rsqrtf(fmaf(fmaf(A, s, 2.0f * B), s, C) + EPS);
    }
    __syncthreads();

    // ---- epilogue: fixed column per thread, constants loaded ONCE ----
    if (tid < 192) {
        const float4 G1 = reinterpret_cast<const float4*>(g_g1)[tid];
        const float4 G2 = reinterpret_cast<const float4*>(g_g2)[tid];
        const float4 BE = reinterpret_cast<const float4*>(g_bt)[tid];
        float4* orow = out + (size_t)blockIdx.x * 16 * 192 + tid;

        #pragma unroll
        for (int r = 0; r < 16; r++) {
            const float s   = SS[r];
            const float inv = SI[r];
            float4 o;
            o.x = fmaf(fmaf(s, G1.x, G2.x), inv, BE.x);
            o.y = fmaf(fmaf(s, G1.y, G2.y), inv, BE.y);
            o.z = fmaf(fmaf(s, G1.z, G2.z), inv, BE.z);
            o.w = fmaf(fmaf(s, G1.w, G2.w), inv, BE.w);
            __stcs(orow + r * 192, o);
        }
    }
}

// ---------------------------------------------------------------------------
// prep: constants for the collapsed matmul+layernorm (single block)
// ---------------------------------------------------------------------------
__device__ __forceinline__ float block_sum768(float v, float* sh) {
    const int lane = threadIdx.x & 31;
    const int wid  = threadIdx.x >> 5;
    #pragma unroll
    for (int o = 16; o; o >>= 1)
        v += __shfl_xor_sync(0xffffffffu, v, o);
    __syncthreads();
    if (lane == 0) sh[wid] = v;
    __syncthreads();
    if (threadIdx.x == 0) {
        float tt = 0.f;
        #pragma unroll
        for (int i = 0; i < 24; i++) tt += sh[i];
        sh[24] = tt;
    }
    __syncthreads();
    return sh[24];
}

__global__ __launch_bounds__(768) void prep_kernel(const float* __restrict__ W,
                                                   const float* __restrict__ b,
                                                   const float* __restrict__ gamma,
                                                   const float* __restrict__ beta) {
    __shared__ float sh[32];
    const int e = threadIdx.x;

    float wsum = 0.f;
    #pragma unroll 4
    for (int k = 0; k < WROWS; k++)
        wsum += W[k * EMBED + e];
    const float be = b[e];

    const float meanW = block_sum768(wsum, sh) * (1.0f / EMBED);
    const float meanb = block_sum768(be,   sh) * (1.0f / EMBED);

    const float u = wsum - meanW;
    const float v = be   - meanb;

    const float A = block_sum768(u * u, sh) * (1.0f / EMBED);
    const float B = block_sum768(u * v, sh) * (1.0f / EMBED);
    const float C = block_sum768(v * v, sh) * (1.0f / EMBED);

    g_g1[e] = u * gamma[e];
    g_g2[e] = v * gamma[e];
    g_bt[e] = beta[e];
    if (e == 0) {
        g_coef[0] = A; g_coef[1] = B; g_coef[2] = C;
    }
}

// ---------------------------------------------------------------------------
extern "C" void kernel_launch(void* const* d_in, const int* in_sizes, int n_in,
                              void* d_out, int out_size) {
    const float* x     = (const float*)d_in[0];
    const float* W     = (const float*)d_in[1];
    const float* b     = (const float*)d_in[2];
    const float* gamma = (const float*)d_in[3];
    const float* beta  = (const float*)d_in[4];

    prep_kernel<<<1, EMBED>>>(W, b, gamma, beta);
    fused_kernel<<<NPATCH / 16, 256>>>(x, (float4*)d_out);
}